// round 13
// baseline (speedup 1.0000x reference)
#include <cuda_runtime.h>
#include <cstdint>

// Problem constants
#define N_USERS  100000
#define N_ITEMS  50000
#define DIM      64
#define QR       5
#define NNZ      2000000

#define KEEP0_BIT 0x40000000
#define KEEP1_BIT 0x80000000u
#define PARTNER_MASK 0x3FFFFFFF

// block counts (all 256-thread blocks unless noted)
#define E_BLOCKS   7813          // ceil(NNZ/256)
#define U_BLOCKS   6250          // N_USERS/2 rows-per-warp * 32 / 256
#define I_BLOCKS   3125
#define QD_BLOCKS  512
#define AUGU_BLOCKS 25000        // N_USERS*64/256
#define AUGI_BLOCKS 12500
#define NORMU_BLOCKS 12500       // N_USERS*32/256
#define NORMI_BLOCKS 6250

// ---------------- device scratch (no allocs allowed) ----------------
__device__ float g_Zu0[N_USERS * DIM];
__device__ float g_Zi0[N_ITEMS * DIM];
__device__ float g_Zu1[N_USERS * DIM];
__device__ float g_Zi1[N_ITEMS * DIM];
__device__ float g_tmp[4 * QR * DIM];
__device__ int  g_rowPtr[N_USERS + 1];
__device__ int  g_colPtr[N_ITEMS + 1];
__device__ int  g_rowCnt[N_USERS];
__device__ int  g_colCnt[N_ITEMS];
__device__ int  g_posRC[NNZ];     // low 16: slot in row, high 16: slot in col
__device__ int2 g_rowEdges[NNZ];  // (partner|keep0<<30|keep1<<31, val/0.75)
__device__ int2 g_colEdges[NNZ];

// ---------------- threefry2x32 (JAX-exact, 20 rounds) ----------------
#define TF_ROUND(r) { x0 += x1; x1 = (x1 << (r)) | (x1 >> (32 - (r))); x1 ^= x0; }

__host__ __device__ inline void tf2x32(uint32_t k0, uint32_t k1,
                                       uint32_t x0, uint32_t x1,
                                       uint32_t& o0, uint32_t& o1) {
    uint32_t ks0 = k0, ks1 = k1, ks2 = k0 ^ k1 ^ 0x1BD11BDAu;
    x0 += ks0; x1 += ks1;
    TF_ROUND(13) TF_ROUND(15) TF_ROUND(26) TF_ROUND(6)
    x0 += ks1; x1 += ks2 + 1u;
    TF_ROUND(17) TF_ROUND(29) TF_ROUND(16) TF_ROUND(24)
    x0 += ks2; x1 += ks0 + 2u;
    TF_ROUND(13) TF_ROUND(15) TF_ROUND(26) TF_ROUND(6)
    x0 += ks0; x1 += ks1 + 3u;
    TF_ROUND(17) TF_ROUND(29) TF_ROUND(16) TF_ROUND(24)
    x0 += ks1; x1 += ks2 + 4u;
    TF_ROUND(13) TF_ROUND(15) TF_ROUND(26) TF_ROUND(6)
    x0 += ks2; x1 += ks0 + 5u;
    o0 = x0; o1 = x1;
}

__device__ inline float bits_to_unit(uint32_t b) {
    return __uint_as_float((b >> 9) | 0x3f800000u) - 1.0f;
}

__device__ inline uint32_t keep_bit(uint32_t ka, uint32_t kb, uint32_t e) {
    uint32_t o0, o1;
    tf2x32(ka, kb, 0u, e, o0, o1);
    return (bits_to_unit(o0 ^ o1) < 0.75f) ? 1u : 0u;
}

// ---------------- device work functions ----------------
__device__ __forceinline__ void dev_hist(const int* __restrict__ rows,
                                         const int* __restrict__ cols,
                                         int vb) {
    int e = vb * 256 + threadIdx.x;
    if (e >= NNZ) return;
    int pr = atomicAdd(&g_rowCnt[__ldg(&rows[e])], 1);
    int pc = atomicAdd(&g_colCnt[__ldg(&cols[e])], 1);
    g_posRC[e] = pr | (pc << 16);
}

// rank-Q projection partial: out[q][d] += sum over this group's n of W[q][n]*E[n][d]
__device__ __forceinline__ void dev_qd(const float* __restrict__ W,
                                       const float* __restrict__ E,
                                       float* __restrict__ out, int N, int vb) {
    __shared__ float red[4][QR][DIM];
    int tid = threadIdx.x;
    int d   = tid & 63;
    int grp = tid >> 6;
    int nGroups = QD_BLOCKS * 4;
    int gid = vb * 4 + grp;
    float acc[QR] = {0.f, 0.f, 0.f, 0.f, 0.f};
    #pragma unroll 8
    for (int n = gid; n < N; n += nGroups) {
        float e = __ldg(&E[(size_t)n * DIM + d]);
        #pragma unroll
        for (int q = 0; q < QR; q++)
            acc[q] += __ldg(&W[(size_t)q * N + n]) * e;
    }
    #pragma unroll
    for (int q = 0; q < QR; q++)
        red[grp][q][d] = acc[q];
    __syncthreads();
    for (int j = tid; j < QR * DIM; j += 256) {
        int q = j >> 6, dd = j & 63;
        atomicAdd(&out[j], red[0][q][dd] + red[1][q][dd] + red[2][q][dd] + red[3][q][dd]);
    }
}

// Pull SPMM: half-warp per row, fully-unrolled 16-edge batches with uniform
// predicates -> up to 16 independent gathers in flight per row-half.
__device__ __forceinline__ void dev_spmm(const int* __restrict__ ptr,
                                         const int2* __restrict__ edges,
                                         const float* __restrict__ E,
                                         float* __restrict__ Z,
                                         uint32_t keepMask, int nrows, int vb) {
    int gtid = vb * 256 + threadIdx.x;
    int gw   = gtid >> 5;
    int lane = threadIdx.x & 31;
    int half = lane >> 4, l16 = lane & 15;
    int row = gw * 2 + half;
    if (row >= nrows) return;
    unsigned gmask = half ? 0xFFFF0000u : 0x0000FFFFu;
    int src = half << 4;
    int s = __ldg(&ptr[row]);
    int t = __ldg(&ptr[row + 1]);
    float4 acc = make_float4(0.f, 0.f, 0.f, 0.f);

    for (int j = s; j < t; j += 16) {
        int idx = j + l16;
        float val = 0.0f; int g = 0;
        if (idx < t) {
            int2 ed = __ldg(&edges[idx]);
            g = ed.x & PARTNER_MASK;
            if ((uint32_t)ed.x & keepMask) val = __int_as_float(ed.y);
        }
        int lim = t - j;          // uniform within the 16-lane group
        #pragma unroll
        for (int k = 0; k < 16; k++) {
            if (k < lim) {
                float v  = __shfl_sync(gmask, val, src + k);
                int   gg = __shfl_sync(gmask, g,   src + k);
                if (v != 0.0f) {
                    float4 x = __ldg(reinterpret_cast<const float4*>(E + (size_t)gg * DIM) + l16);
                    acc.x += v * x.x; acc.y += v * x.y;
                    acc.z += v * x.z; acc.w += v * x.w;
                }
            }
        }
    }
    reinterpret_cast<float4*>(Z + (size_t)row * DIM)[l16] = acc;
}

__device__ __forceinline__ void dev_aug(const float* __restrict__ E0,
                                        const float* __restrict__ S,
                                        const float* __restrict__ tA,
                                        const float* __restrict__ tB,
                                        float* __restrict__ out, int nrows, int vb) {
    __shared__ float t[QR * DIM];
    for (int j = threadIdx.x; j < QR * DIM; j += 256)
        t[j] = tA[j] + tB[j];
    __syncthreads();
    int idx = vb * 256 + threadIdx.x;
    if (idx >= nrows * DIM) return;
    int row = idx >> 6, d = idx & 63;
    float acc = E0[idx];
    #pragma unroll
    for (int q = 0; q < QR; q++)
        acc += __ldg(&S[row * QR + q]) * t[q * DIM + d];
    out[idx] = acc;
}

__device__ __forceinline__ void dev_norm(const float* __restrict__ E0,
                                         const float* __restrict__ Z0,
                                         const float* __restrict__ Z1,
                                         float* __restrict__ out, int nrows, int vb) {
    int gwarp = (vb * 256 + threadIdx.x) >> 5;
    int lane  = threadIdx.x & 31;
    if (gwarp >= nrows) return;
    size_t base = (size_t)gwarp * DIM + lane * 2;
    float2 a = *reinterpret_cast<const float2*>(E0 + base);
    float2 b = *reinterpret_cast<const float2*>(Z0 + base);
    float2 c = *reinterpret_cast<const float2*>(Z1 + base);
    float x = a.x + b.x + c.x;
    float y = a.y + b.y + c.y;
    float ss = x * x + y * y;
    #pragma unroll
    for (int o = 16; o; o >>= 1) ss += __shfl_xor_sync(0xFFFFFFFFu, ss, o);
    float inv = rsqrtf(ss);
    float2 r; r.x = x * inv; r.y = y * inv;
    *reinterpret_cast<float2*>(out + base) = r;
}

// ---------------- fused dispatcher kernels ----------------
// K1: hist + qd0(vt@E_i0) + qd1(ut@E_u0)
__global__ void k_hist_qd(const int* rows, const int* cols,
                          const float* vt, const float* E_i_0,
                          const float* ut, const float* E_u_0) {
    int b = blockIdx.x;
    if (b < E_BLOCKS)                 dev_hist(rows, cols, b);
    else if (b < E_BLOCKS + QD_BLOCKS) dev_qd(vt, E_i_0, g_tmp + 0 * QR * DIM, N_ITEMS, b - E_BLOCKS);
    else                               dev_qd(ut, E_u_0, g_tmp + 1 * QR * DIM, N_USERS, b - E_BLOCKS - QD_BLOCKS);
}

// K2: both exclusive scans (block 0 = rows, block 1 = cols), 1024 threads
__global__ void k_scan2() {
    const int* cnt = blockIdx.x ? g_colCnt : g_rowCnt;
    int*       ptr = blockIdx.x ? g_colPtr : g_rowPtr;
    int n          = blockIdx.x ? N_ITEMS  : N_USERS;
    __shared__ int warpSum[32];
    __shared__ int warpPre[32];
    __shared__ int running;
    int tid = threadIdx.x, lane = tid & 31, wid = tid >> 5;
    if (tid == 0) running = 0;
    __syncthreads();
    for (int base = 0; base < n; base += 1024) {
        int i = base + tid;
        int v = (i < n) ? cnt[i] : 0;
        int x = v;
        #pragma unroll
        for (int off = 1; off < 32; off <<= 1) {
            int t = __shfl_up_sync(0xFFFFFFFFu, x, off);
            if (lane >= off) x += t;
        }
        if (lane == 31) warpSum[wid] = x;
        __syncthreads();
        if (wid == 0) {
            int w = warpSum[lane];
            int xs = w;
            #pragma unroll
            for (int off = 1; off < 32; off <<= 1) {
                int t = __shfl_up_sync(0xFFFFFFFFu, xs, off);
                if (lane >= off) xs += t;
            }
            warpPre[lane] = xs - w;
        }
        __syncthreads();
        int run = running;
        if (i < n) ptr[i] = run + warpPre[wid] + x - v;
        __syncthreads();
        if (tid == 0) running = run + warpPre[31] + warpSum[31];
        __syncthreads();
    }
    if (threadIdx.x == 0) ptr[n] = running;
}

// K3: fill (scattered 8B stores, keep-bits baked)
__global__ void k_fill(const int* __restrict__ rows, const int* __restrict__ cols,
                       const float* __restrict__ vals,
                       uint32_t r0a, uint32_t r0b, uint32_t r1a, uint32_t r1b,
                       uint32_t c0a, uint32_t c0b, uint32_t c1a, uint32_t c1b) {
    int e = blockIdx.x * blockDim.x + threadIdx.x;
    if (e >= NNZ) return;
    int r = __ldg(&rows[e]), c = __ldg(&cols[e]);
    int vi = __float_as_int(__ldg(&vals[e]) * (1.0f / 0.75f));
    uint32_t ue = (uint32_t)e;
    uint32_t kr = (keep_bit(r0a, r0b, ue) << 30) | (keep_bit(r1a, r1b, ue) << 31);
    uint32_t kc = (keep_bit(c0a, c0b, ue) << 30) | (keep_bit(c1a, c1b, ue) << 31);
    int p = __ldg(&g_posRC[e]);
    g_rowEdges[__ldg(&g_rowPtr[r]) + (p & 0xFFFF)]         = make_int2((int)(c | kr), vi);
    g_colEdges[__ldg(&g_colPtr[c]) + ((p >> 16) & 0xFFFF)] = make_int2((int)(r | kc), vi);
}

// K4: layer-0 SPMMs (user + item fused)
__global__ void __launch_bounds__(256, 4) k_layer0(const float* E_u_0, const float* E_i_0) {
    int b = blockIdx.x;
    if (b < U_BLOCKS) dev_spmm(g_rowPtr, g_rowEdges, E_i_0, g_Zu0, KEEP0_BIT, N_USERS, b);
    else              dev_spmm(g_colPtr, g_colEdges, E_u_0, g_Zi0, KEEP0_BIT, N_ITEMS, b - U_BLOCKS);
}

// K5: layer-1 SPMMs + qd2(vt@Zi0) + qd3(ut@Zu0)
__global__ void __launch_bounds__(256, 4) k_layer1(const float* vt, const float* ut) {
    int b = blockIdx.x;
    if (b < U_BLOCKS)
        dev_spmm(g_rowPtr, g_rowEdges, g_Zi0, g_Zu1, KEEP1_BIT, N_USERS, b);
    else if (b < U_BLOCKS + I_BLOCKS)
        dev_spmm(g_colPtr, g_colEdges, g_Zu0, g_Zi1, KEEP1_BIT, N_ITEMS, b - U_BLOCKS);
    else if (b < U_BLOCKS + I_BLOCKS + QD_BLOCKS)
        dev_qd(vt, g_Zi0, g_tmp + 2 * QR * DIM, N_ITEMS, b - U_BLOCKS - I_BLOCKS);
    else
        dev_qd(ut, g_Zu0, g_tmp + 3 * QR * DIM, N_USERS, b - U_BLOCKS - I_BLOCKS - QD_BLOCKS);
}

// K6: epilogue — aug_u, aug_i, norm_u, norm_i fused
__global__ void k_epilogue(const float* E_u_0, const float* E_i_0,
                           const float* u_mul_s, const float* v_mul_s,
                           float* out_main, float* out_aug) {
    int b = blockIdx.x;
    if (b < AUGU_BLOCKS)
        dev_aug(E_u_0, u_mul_s, g_tmp + 0 * QR * DIM, g_tmp + 2 * QR * DIM,
                out_aug, N_USERS, b);
    else if (b < AUGU_BLOCKS + AUGI_BLOCKS)
        dev_aug(E_i_0, v_mul_s, g_tmp + 1 * QR * DIM, g_tmp + 3 * QR * DIM,
                out_aug + (size_t)N_USERS * DIM, N_ITEMS, b - AUGU_BLOCKS);
    else if (b < AUGU_BLOCKS + AUGI_BLOCKS + NORMU_BLOCKS)
        dev_norm(E_u_0, g_Zu0, g_Zu1, out_main, N_USERS,
                 b - AUGU_BLOCKS - AUGI_BLOCKS);
    else
        dev_norm(E_i_0, g_Zi0, g_Zi1, out_main + (size_t)N_USERS * DIM, N_ITEMS,
                 b - AUGU_BLOCKS - AUGI_BLOCKS - NORMU_BLOCKS);
}

// ---------------- host ----------------
static void host_split3(uint32_t k0, uint32_t k1, uint32_t out[3][2]) {
    for (uint32_t i = 0; i < 3; i++)
        tf2x32(k0, k1, 0u, i, out[i][0], out[i][1]);
}

extern "C" void kernel_launch(void* const* d_in, const int* in_sizes, int n_in,
                              void* d_out, int out_size) {
    const float* adj_vals = (const float*)d_in[0];
    const float* E_u_0    = (const float*)d_in[1];
    const float* E_i_0    = (const float*)d_in[2];
    const float* u_mul_s  = (const float*)d_in[3];
    const float* vt       = (const float*)d_in[4];
    const float* v_mul_s  = (const float*)d_in[5];
    const float* ut       = (const float*)d_in[6];
    const int*   adj_rows = (const int*)d_in[7];
    const int*   adj_cols = (const int*)d_in[8];
    float* out_main = (float*)d_out;
    float* out_aug  = (float*)d_out + (size_t)(N_USERS + N_ITEMS) * DIM;

    uint32_t s0[3][2], s1[3][2];
    host_split3(0u, 42u, s0);                 // key(42) -> k1_0, k2_0, dkey
    host_split3(s0[2][0], s0[2][1], s1);      // dkey   -> k1_1, k2_1, _

    void *pRowCnt, *pColCnt, *pTmp;
    cudaGetSymbolAddress(&pRowCnt, g_rowCnt);
    cudaGetSymbolAddress(&pColCnt, g_colCnt);
    cudaGetSymbolAddress(&pTmp, g_tmp);
    cudaMemsetAsync(pRowCnt, 0, sizeof(int) * N_USERS, 0);
    cudaMemsetAsync(pColCnt, 0, sizeof(int) * N_ITEMS, 0);
    cudaMemsetAsync(pTmp, 0, sizeof(float) * 4 * QR * DIM, 0);

    // K1: hist + layer-0 rank-Q projections (independent work overlapped)
    k_hist_qd<<<E_BLOCKS + 2 * QD_BLOCKS, 256>>>(adj_rows, adj_cols,
                                                 vt, E_i_0, ut, E_u_0);
    // K2: both scans
    k_scan2<<<2, 1024>>>();
    // K3: fill CSR with baked keep-bits
    k_fill<<<E_BLOCKS, 256>>>(adj_rows, adj_cols, adj_vals,
                              s0[0][0], s0[0][1], s1[0][0], s1[0][1],
                              s0[1][0], s0[1][1], s1[1][0], s1[1][1]);
    // K4: layer-0 SPMMs
    k_layer0<<<U_BLOCKS + I_BLOCKS, 256>>>(E_u_0, E_i_0);
    // K5: layer-1 SPMMs + layer-1 rank-Q projections
    k_layer1<<<U_BLOCKS + I_BLOCKS + 2 * QD_BLOCKS, 256>>>(vt, ut);
    // K6: epilogue
    k_epilogue<<<AUGU_BLOCKS + AUGI_BLOCKS + NORMU_BLOCKS + NORMI_BLOCKS, 256>>>(
        E_u_0, E_i_0, u_mul_s, v_mul_s, out_main, out_aug);
}

// round 14
// speedup vs baseline: 1.3072x; 1.3072x over previous
#include <cuda_runtime.h>
#include <cstdint>

// Problem constants
#define N_USERS  100000
#define N_ITEMS  50000
#define DIM      64
#define QR       5
#define NNZ      2000000

#define KEEP0_BIT 0x40000000
#define KEEP1_BIT 0x80000000u
#define PARTNER_MASK 0x3FFFFFFF

// block counts (all 256-thread blocks unless noted)
#define E_BLOCKS   7813          // ceil(NNZ/256)
#define U_BLOCKS   6250          // N_USERS/2 rows-per-warp * 32 / 256
#define I_BLOCKS   3125
#define QD_BLOCKS  512
#define AUGU_BLOCKS 25000        // N_USERS*64/256
#define AUGI_BLOCKS 12500
#define NORMU_BLOCKS 12500       // N_USERS*32/256
#define NORMI_BLOCKS 6250

// ---------------- device scratch (no allocs allowed) ----------------
__device__ float g_Zu0[N_USERS * DIM];
__device__ float g_Zi0[N_ITEMS * DIM];
__device__ float g_Zu1[N_USERS * DIM];
__device__ float g_Zi1[N_ITEMS * DIM];
__device__ float g_tmp[4 * QR * DIM];
__device__ int  g_rowPtr[N_USERS + 1];
__device__ int  g_colPtr[N_ITEMS + 1];
__device__ int  g_rowCnt[N_USERS];
__device__ int  g_colCnt[N_ITEMS];
__device__ int  g_posRC[NNZ];     // low 16: slot in row, high 16: slot in col
__device__ int2 g_rowEdges[NNZ];  // (partner|keep0<<30|keep1<<31, val/0.75)
__device__ int2 g_colEdges[NNZ];

// ---------------- threefry2x32 (JAX-exact, 20 rounds) ----------------
#define TF_ROUND(r) { x0 += x1; x1 = (x1 << (r)) | (x1 >> (32 - (r))); x1 ^= x0; }

__host__ __device__ inline void tf2x32(uint32_t k0, uint32_t k1,
                                       uint32_t x0, uint32_t x1,
                                       uint32_t& o0, uint32_t& o1) {
    uint32_t ks0 = k0, ks1 = k1, ks2 = k0 ^ k1 ^ 0x1BD11BDAu;
    x0 += ks0; x1 += ks1;
    TF_ROUND(13) TF_ROUND(15) TF_ROUND(26) TF_ROUND(6)
    x0 += ks1; x1 += ks2 + 1u;
    TF_ROUND(17) TF_ROUND(29) TF_ROUND(16) TF_ROUND(24)
    x0 += ks2; x1 += ks0 + 2u;
    TF_ROUND(13) TF_ROUND(15) TF_ROUND(26) TF_ROUND(6)
    x0 += ks0; x1 += ks1 + 3u;
    TF_ROUND(17) TF_ROUND(29) TF_ROUND(16) TF_ROUND(24)
    x0 += ks1; x1 += ks2 + 4u;
    TF_ROUND(13) TF_ROUND(15) TF_ROUND(26) TF_ROUND(6)
    x0 += ks2; x1 += ks0 + 5u;
    o0 = x0; o1 = x1;
}

__device__ inline float bits_to_unit(uint32_t b) {
    return __uint_as_float((b >> 9) | 0x3f800000u) - 1.0f;
}

__device__ inline uint32_t keep_bit(uint32_t ka, uint32_t kb, uint32_t e) {
    uint32_t o0, o1;
    tf2x32(ka, kb, 0u, e, o0, o1);
    return (bits_to_unit(o0 ^ o1) < 0.75f) ? 1u : 0u;
}

// ---------------- device work functions ----------------
__device__ __forceinline__ void dev_hist(const int* __restrict__ rows,
                                         const int* __restrict__ cols,
                                         int vb) {
    int e = vb * 256 + threadIdx.x;
    if (e >= NNZ) return;
    int pr = atomicAdd(&g_rowCnt[__ldg(&rows[e])], 1);
    int pc = atomicAdd(&g_colCnt[__ldg(&cols[e])], 1);
    g_posRC[e] = pr | (pc << 16);
}

// rank-Q projection partial: out[q][d] += sum over this group's n of W[q][n]*E[n][d]
__device__ __forceinline__ void dev_qd(const float* __restrict__ W,
                                       const float* __restrict__ E,
                                       float* __restrict__ out, int N, int vb) {
    __shared__ float red[4][QR][DIM];
    int tid = threadIdx.x;
    int d   = tid & 63;
    int grp = tid >> 6;
    int nGroups = QD_BLOCKS * 4;
    int gid = vb * 4 + grp;
    float acc[QR] = {0.f, 0.f, 0.f, 0.f, 0.f};
    #pragma unroll 8
    for (int n = gid; n < N; n += nGroups) {
        float e = __ldg(&E[(size_t)n * DIM + d]);
        #pragma unroll
        for (int q = 0; q < QR; q++)
            acc[q] += __ldg(&W[(size_t)q * N + n]) * e;
    }
    #pragma unroll
    for (int q = 0; q < QR; q++)
        red[grp][q][d] = acc[q];
    __syncthreads();
    for (int j = tid; j < QR * DIM; j += 256) {
        int q = j >> 6, dd = j & 63;
        atomicAdd(&out[j], red[0][q][dd] + red[1][q][dd] + red[2][q][dd] + red[3][q][dd]);
    }
}

// Pull SPMM: half-warp (16 lanes) per row, float4 accumulator per lane.
// Edge record loaded by ALL 16 lanes at the same address (broadcast LDG,
// sequential addresses -> L1 line hits). No shuffles, no batch staging.
// unroll 4 -> 4 independent edge loads + 4 independent gathers in flight.
__device__ __forceinline__ void dev_spmm(const int* __restrict__ ptr,
                                         const int2* __restrict__ edges,
                                         const float* __restrict__ E,
                                         float* __restrict__ Z,
                                         uint32_t keepMask, int nrows, int vb) {
    int gtid = vb * 256 + threadIdx.x;
    int gw   = gtid >> 5;
    int lane = threadIdx.x & 31;
    int half = lane >> 4, l16 = lane & 15;
    int row = gw * 2 + half;
    if (row >= nrows) return;
    int s = __ldg(&ptr[row]);
    int t = __ldg(&ptr[row + 1]);
    float4 acc = make_float4(0.f, 0.f, 0.f, 0.f);

    #pragma unroll 4
    for (int k = s; k < t; k++) {
        int2 ed = __ldg(&edges[k]);           // broadcast within 16-lane group
        if ((uint32_t)ed.x & keepMask) {
            float v  = __int_as_float(ed.y);
            int   gg = ed.x & PARTNER_MASK;
            float4 x = __ldg(reinterpret_cast<const float4*>(E + (size_t)gg * DIM) + l16);
            acc.x += v * x.x; acc.y += v * x.y;
            acc.z += v * x.z; acc.w += v * x.w;
        }
    }
    reinterpret_cast<float4*>(Z + (size_t)row * DIM)[l16] = acc;
}

__device__ __forceinline__ void dev_aug(const float* __restrict__ E0,
                                        const float* __restrict__ S,
                                        const float* __restrict__ tA,
                                        const float* __restrict__ tB,
                                        float* __restrict__ out, int nrows, int vb) {
    __shared__ float t[QR * DIM];
    for (int j = threadIdx.x; j < QR * DIM; j += 256)
        t[j] = tA[j] + tB[j];
    __syncthreads();
    int idx = vb * 256 + threadIdx.x;
    if (idx >= nrows * DIM) return;
    int row = idx >> 6, d = idx & 63;
    float acc = E0[idx];
    #pragma unroll
    for (int q = 0; q < QR; q++)
        acc += __ldg(&S[row * QR + q]) * t[q * DIM + d];
    out[idx] = acc;
}

__device__ __forceinline__ void dev_norm(const float* __restrict__ E0,
                                         const float* __restrict__ Z0,
                                         const float* __restrict__ Z1,
                                         float* __restrict__ out, int nrows, int vb) {
    int gwarp = (vb * 256 + threadIdx.x) >> 5;
    int lane  = threadIdx.x & 31;
    if (gwarp >= nrows) return;
    size_t base = (size_t)gwarp * DIM + lane * 2;
    float2 a = *reinterpret_cast<const float2*>(E0 + base);
    float2 b = *reinterpret_cast<const float2*>(Z0 + base);
    float2 c = *reinterpret_cast<const float2*>(Z1 + base);
    float x = a.x + b.x + c.x;
    float y = a.y + b.y + c.y;
    float ss = x * x + y * y;
    #pragma unroll
    for (int o = 16; o; o >>= 1) ss += __shfl_xor_sync(0xFFFFFFFFu, ss, o);
    float inv = rsqrtf(ss);
    float2 r; r.x = x * inv; r.y = y * inv;
    *reinterpret_cast<float2*>(out + base) = r;
}

// ---------------- fused dispatcher kernels ----------------
// K1: hist + qd0(vt@E_i0) + qd1(ut@E_u0)
__global__ void k_hist_qd(const int* rows, const int* cols,
                          const float* vt, const float* E_i_0,
                          const float* ut, const float* E_u_0) {
    int b = blockIdx.x;
    if (b < E_BLOCKS)                 dev_hist(rows, cols, b);
    else if (b < E_BLOCKS + QD_BLOCKS) dev_qd(vt, E_i_0, g_tmp + 0 * QR * DIM, N_ITEMS, b - E_BLOCKS);
    else                               dev_qd(ut, E_u_0, g_tmp + 1 * QR * DIM, N_USERS, b - E_BLOCKS - QD_BLOCKS);
}

// K2: both exclusive scans (block 0 = rows, block 1 = cols), 1024 threads
__global__ void k_scan2() {
    const int* cnt = blockIdx.x ? g_colCnt : g_rowCnt;
    int*       ptr = blockIdx.x ? g_colPtr : g_rowPtr;
    int n          = blockIdx.x ? N_ITEMS  : N_USERS;
    __shared__ int warpSum[32];
    __shared__ int warpPre[32];
    __shared__ int running;
    int tid = threadIdx.x, lane = tid & 31, wid = tid >> 5;
    if (tid == 0) running = 0;
    __syncthreads();
    for (int base = 0; base < n; base += 1024) {
        int i = base + tid;
        int v = (i < n) ? cnt[i] : 0;
        int x = v;
        #pragma unroll
        for (int off = 1; off < 32; off <<= 1) {
            int t = __shfl_up_sync(0xFFFFFFFFu, x, off);
            if (lane >= off) x += t;
        }
        if (lane == 31) warpSum[wid] = x;
        __syncthreads();
        if (wid == 0) {
            int w = warpSum[lane];
            int xs = w;
            #pragma unroll
            for (int off = 1; off < 32; off <<= 1) {
                int t = __shfl_up_sync(0xFFFFFFFFu, xs, off);
                if (lane >= off) xs += t;
            }
            warpPre[lane] = xs - w;
        }
        __syncthreads();
        int run = running;
        if (i < n) ptr[i] = run + warpPre[wid] + x - v;
        __syncthreads();
        if (tid == 0) running = run + warpPre[31] + warpSum[31];
        __syncthreads();
    }
    if (threadIdx.x == 0) ptr[n] = running;
}

// K3: fill (scattered 8B stores, keep-bits baked)
__global__ void k_fill(const int* __restrict__ rows, const int* __restrict__ cols,
                       const float* __restrict__ vals,
                       uint32_t r0a, uint32_t r0b, uint32_t r1a, uint32_t r1b,
                       uint32_t c0a, uint32_t c0b, uint32_t c1a, uint32_t c1b) {
    int e = blockIdx.x * blockDim.x + threadIdx.x;
    if (e >= NNZ) return;
    int r = __ldg(&rows[e]), c = __ldg(&cols[e]);
    int vi = __float_as_int(__ldg(&vals[e]) * (1.0f / 0.75f));
    uint32_t ue = (uint32_t)e;
    uint32_t kr = (keep_bit(r0a, r0b, ue) << 30) | (keep_bit(r1a, r1b, ue) << 31);
    uint32_t kc = (keep_bit(c0a, c0b, ue) << 30) | (keep_bit(c1a, c1b, ue) << 31);
    int p = __ldg(&g_posRC[e]);
    g_rowEdges[__ldg(&g_rowPtr[r]) + (p & 0xFFFF)]         = make_int2((int)(c | kr), vi);
    g_colEdges[__ldg(&g_colPtr[c]) + ((p >> 16) & 0xFFFF)] = make_int2((int)(r | kc), vi);
}

// K4: layer-0 SPMMs (user + item fused)
__global__ void k_layer0(const float* E_u_0, const float* E_i_0) {
    int b = blockIdx.x;
    if (b < U_BLOCKS) dev_spmm(g_rowPtr, g_rowEdges, E_i_0, g_Zu0, KEEP0_BIT, N_USERS, b);
    else              dev_spmm(g_colPtr, g_colEdges, E_u_0, g_Zi0, KEEP0_BIT, N_ITEMS, b - U_BLOCKS);
}

// K5: layer-1 SPMMs + qd2(vt@Zi0) + qd3(ut@Zu0)
__global__ void k_layer1(const float* vt, const float* ut) {
    int b = blockIdx.x;
    if (b < U_BLOCKS)
        dev_spmm(g_rowPtr, g_rowEdges, g_Zi0, g_Zu1, KEEP1_BIT, N_USERS, b);
    else if (b < U_BLOCKS + I_BLOCKS)
        dev_spmm(g_colPtr, g_colEdges, g_Zu0, g_Zi1, KEEP1_BIT, N_ITEMS, b - U_BLOCKS);
    else if (b < U_BLOCKS + I_BLOCKS + QD_BLOCKS)
        dev_qd(vt, g_Zi0, g_tmp + 2 * QR * DIM, N_ITEMS, b - U_BLOCKS - I_BLOCKS);
    else
        dev_qd(ut, g_Zu0, g_tmp + 3 * QR * DIM, N_USERS, b - U_BLOCKS - I_BLOCKS - QD_BLOCKS);
}

// K6: epilogue — aug_u, aug_i, norm_u, norm_i fused
__global__ void k_epilogue(const float* E_u_0, const float* E_i_0,
                           const float* u_mul_s, const float* v_mul_s,
                           float* out_main, float* out_aug) {
    int b = blockIdx.x;
    if (b < AUGU_BLOCKS)
        dev_aug(E_u_0, u_mul_s, g_tmp + 0 * QR * DIM, g_tmp + 2 * QR * DIM,
                out_aug, N_USERS, b);
    else if (b < AUGU_BLOCKS + AUGI_BLOCKS)
        dev_aug(E_i_0, v_mul_s, g_tmp + 1 * QR * DIM, g_tmp + 3 * QR * DIM,
                out_aug + (size_t)N_USERS * DIM, N_ITEMS, b - AUGU_BLOCKS);
    else if (b < AUGU_BLOCKS + AUGI_BLOCKS + NORMU_BLOCKS)
        dev_norm(E_u_0, g_Zu0, g_Zu1, out_main, N_USERS,
                 b - AUGU_BLOCKS - AUGI_BLOCKS);
    else
        dev_norm(E_i_0, g_Zi0, g_Zi1, out_main + (size_t)N_USERS * DIM, N_ITEMS,
                 b - AUGU_BLOCKS - AUGI_BLOCKS - NORMU_BLOCKS);
}

// ---------------- host ----------------
static void host_split3(uint32_t k0, uint32_t k1, uint32_t out[3][2]) {
    for (uint32_t i = 0; i < 3; i++)
        tf2x32(k0, k1, 0u, i, out[i][0], out[i][1]);
}

extern "C" void kernel_launch(void* const* d_in, const int* in_sizes, int n_in,
                              void* d_out, int out_size) {
    const float* adj_vals = (const float*)d_in[0];
    const float* E_u_0    = (const float*)d_in[1];
    const float* E_i_0    = (const float*)d_in[2];
    const float* u_mul_s  = (const float*)d_in[3];
    const float* vt       = (const float*)d_in[4];
    const float* v_mul_s  = (const float*)d_in[5];
    const float* ut       = (const float*)d_in[6];
    const int*   adj_rows = (const int*)d_in[7];
    const int*   adj_cols = (const int*)d_in[8];
    float* out_main = (float*)d_out;
    float* out_aug  = (float*)d_out + (size_t)(N_USERS + N_ITEMS) * DIM;

    uint32_t s0[3][2], s1[3][2];
    host_split3(0u, 42u, s0);                 // key(42) -> k1_0, k2_0, dkey
    host_split3(s0[2][0], s0[2][1], s1);      // dkey   -> k1_1, k2_1, _

    void *pRowCnt, *pColCnt, *pTmp;
    cudaGetSymbolAddress(&pRowCnt, g_rowCnt);
    cudaGetSymbolAddress(&pColCnt, g_colCnt);
    cudaGetSymbolAddress(&pTmp, g_tmp);
    cudaMemsetAsync(pRowCnt, 0, sizeof(int) * N_USERS, 0);
    cudaMemsetAsync(pColCnt, 0, sizeof(int) * N_ITEMS, 0);
    cudaMemsetAsync(pTmp, 0, sizeof(float) * 4 * QR * DIM, 0);

    // K1: hist + layer-0 rank-Q projections (independent work overlapped)
    k_hist_qd<<<E_BLOCKS + 2 * QD_BLOCKS, 256>>>(adj_rows, adj_cols,
                                                 vt, E_i_0, ut, E_u_0);
    // K2: both scans
    k_scan2<<<2, 1024>>>();
    // K3: fill CSR with baked keep-bits
    k_fill<<<E_BLOCKS, 256>>>(adj_rows, adj_cols, adj_vals,
                              s0[0][0], s0[0][1], s1[0][0], s1[0][1],
                              s0[1][0], s0[1][1], s1[1][0], s1[1][1]);
    // K4: layer-0 SPMMs
    k_layer0<<<U_BLOCKS + I_BLOCKS, 256>>>(E_u_0, E_i_0);
    // K5: layer-1 SPMMs + layer-1 rank-Q projections
    k_layer1<<<U_BLOCKS + I_BLOCKS + 2 * QD_BLOCKS, 256>>>(vt, ut);
    // K6: epilogue
    k_epilogue<<<AUGU_BLOCKS + AUGI_BLOCKS + NORMU_BLOCKS + NORMI_BLOCKS, 256>>>(
        E_u_0, E_i_0, u_mul_s, v_mul_s, out_main, out_aug);
}